// round 1
// baseline (speedup 1.0000x reference)
#include <cuda_runtime.h>
#include <math.h>

#define B_TOTAL 131072
#define KNB 5
#define TILE_B 16
#define ROWS (TILE_B * KNB)   // 80
#define COMB 128
#define HID 256
#define AH 128                 // HIDDEN/2 (attn hidden)

// ---------------- scratch (no allocs allowed) ----------------
__device__ float g_hbar[(size_t)B_TOTAL * HID];     // 134 MB
__device__ unsigned char g_anyv[B_TOTAL];
__device__ int g_valid_mode;  // 0=int32, 1=uint8(bool), 2=float32

__device__ __forceinline__ float gelu_exact(float x) {
    return 0.5f * x * (1.0f + erff(x * 0.70710678118654752f));
}

// ---------------- valid-dtype probe ----------------
// neighbor_valid is a jax bool; serialization dtype is uncertain.
// uint8 bools: word view has values like 0x01010101 (>1, != 1.0f bits)
// int32 0/1:   words in {0,1}
// float32:     words in {0, 0x3F800000}
// Deterministic (pure function of input data).
__global__ void detect_valid_kernel(const unsigned int* __restrict__ v, int nwords) {
    __shared__ int f_u8, f_f32;
    if (threadIdx.x == 0) { f_u8 = 0; f_f32 = 0; }
    __syncthreads();
    int lu8 = 0, lf32 = 0;
    for (int i = threadIdx.x; i < nwords; i += blockDim.x) {
        unsigned int w = v[i];
        if (w == 0x3F800000u) lf32 = 1;
        else if (w > 1u) lu8 = 1;
    }
    if (lu8) atomicOr(&f_u8, 1);
    if (lf32) atomicOr(&f_f32, 1);
    __syncthreads();
    if (threadIdx.x == 0) {
        g_valid_mode = f_f32 ? 2 : (f_u8 ? 1 : 0);
    }
}

// ---------------- fused featurize + attn + val-W1 + softmax-combine ----------------
// smem layout (floats):
//  combT [128][80]          @ 0       (10240)
//  w1s   [128][256] max     @ 10240   (32768)
//  feat  [80][6]            @ 43008   (480)
//  score [80]               @ 43488
//  wgt   [80]               @ 43568
//  b1s   [256]              @ 43648
//  w2a   [128]              @ 43904
//  cWs   [6][32]            @ 44032
//  cbs   [32]               @ 44224
//  ridx  [80] (int)         @ 44256
//  sidx  [80] (int)         @ 44336
// total 44416 floats = 177664 B
#define SMEM_B_FLOATS 44416
#define SMEM_B_BYTES (SMEM_B_FLOATS * 4)

__global__ void __launch_bounds__(512, 1) fused_kernel(
    const int* __restrict__ res_idx,
    const int* __restrict__ ss_idx,
    const float* __restrict__ dist,
    const int* __restrict__ seq_sep,
    const float* __restrict__ angles,
    const void* __restrict__ validp,
    const float* __restrict__ res_table,
    const float* __restrict__ ss_table,
    const float* __restrict__ cont_W,
    const float* __restrict__ cont_b,
    const float* __restrict__ attn_W1,
    const float* __restrict__ attn_b1,
    const float* __restrict__ attn_W2,
    const float* __restrict__ attn_b2,
    const float* __restrict__ val_W1,
    const float* __restrict__ val_b1)
{
    extern __shared__ float sm[];
    float* combT = sm;                     // [128][80]  combT[c*80 + r]
    float* w1s   = sm + 10240;             // staged weights
    float* feat  = sm + 43008;             // [80][6]
    float* score = sm + 43488;             // [80]
    float* wgt   = sm + 43568;             // [80]
    float* b1s   = sm + 43648;             // [256]
    float* w2a   = sm + 43904;             // [128]
    float* cWs   = sm + 44032;             // [6][32]
    float* cbs   = sm + 44224;             // [32]
    int*   ridx  = (int*)(sm + 44256);     // [80]
    int*   sidx  = (int*)(sm + 44336);     // [80]

    const int tid = threadIdx.x;
    const int b0  = blockIdx.x * TILE_B;
    const int gr0 = b0 * KNB;

    // --- stage small constants + features ---
    for (int i = tid; i < 6 * 32; i += 512) cWs[i] = cont_W[i];
    if (tid < 32) cbs[tid] = cont_b[tid];
    if (tid < AH) { b1s[tid] = attn_b1[tid]; w2a[tid] = attn_W2[tid]; }
    if (tid < ROWS) {
        int gr = gr0 + tid;
        ridx[tid] = res_idx[gr];
        sidx[tid] = ss_idx[gr];
        float d = dist[gr];
        if (d != d) d = 0.0f;
        feat[tid * 6 + 0] = d * (1.0f / 15.0f);
        feat[tid * 6 + 1] = log1pf(fabsf((float)seq_sep[gr])) * 0.2f;
        float4 a = ((const float4*)angles)[gr];
        feat[tid * 6 + 2] = (a.x != a.x) ? 0.0f : a.x;
        feat[tid * 6 + 3] = (a.y != a.y) ? 0.0f : a.y;
        feat[tid * 6 + 4] = (a.z != a.z) ? 0.0f : a.z;
        feat[tid * 6 + 5] = (a.w != a.w) ? 0.0f : a.w;
        score[tid] = 0.0f;
    }
    // stage attn_W1 [128][128]
    for (int i = tid; i < (AH * COMB) / 4; i += 512)
        ((float4*)w1s)[i] = ((const float4*)attn_W1)[i];
    __syncthreads();

    // --- build combined (transposed): res(64) | ss(32) | cont(32) ---
    for (int i = tid; i < ROWS * 64; i += 512) {
        int r = i >> 6, c = i & 63;
        combT[c * ROWS + r] = res_table[ridx[r] * 64 + c];
    }
    for (int i = tid; i < ROWS * 32; i += 512) {
        int r = i >> 5, c = i & 31;
        combT[(64 + c) * ROWS + r] = ss_table[sidx[r] * 32 + c];
    }
    for (int i = tid; i < ROWS * 32; i += 512) {
        int r = i >> 5, c = i & 31;
        float s = cbs[c];
        #pragma unroll
        for (int j = 0; j < 6; j++) s += feat[r * 6 + j] * cWs[j * 32 + c];
        combT[(96 + c) * ROWS + r] = s;
    }
    __syncthreads();

    // --- GEMM1: scores = gelu(combined @ attn_W1 + b1) @ attn_W2 ---
    {
        const int bl = tid & 15;
        const int cg = tid >> 4;         // 0..31
        const int c0 = cg * 4;
        const int r0 = bl * KNB;
        float4 bias = *(const float4*)&b1s[c0];
        float acc[KNB][4];
        #pragma unroll
        for (int i = 0; i < KNB; i++) {
            acc[i][0] = bias.x; acc[i][1] = bias.y; acc[i][2] = bias.z; acc[i][3] = bias.w;
        }
        for (int kk = 0; kk < COMB; kk++) {
            float4 w = *(const float4*)&w1s[kk * AH + c0];
            const float* cb = &combT[kk * ROWS + r0];
            #pragma unroll
            for (int i = 0; i < KNB; i++) {
                float cv = cb[i];
                acc[i][0] += cv * w.x; acc[i][1] += cv * w.y;
                acc[i][2] += cv * w.z; acc[i][3] += cv * w.w;
            }
        }
        float4 wv = *(const float4*)&w2a[c0];
        #pragma unroll
        for (int i = 0; i < KNB; i++) {
            float p = gelu_exact(acc[i][0]) * wv.x + gelu_exact(acc[i][1]) * wv.y
                    + gelu_exact(acc[i][2]) * wv.z + gelu_exact(acc[i][3]) * wv.w;
            atomicAdd(&score[r0 + i], p);
        }
    }
    __syncthreads();

    // --- softmax (threads 0..15) concurrent with val_W1 restage ---
    if (tid < TILE_B) {
        int gb = b0 + tid;
        float ab2 = attn_b2[0];
        int mode = g_valid_mode;
        float s[KNB];
        int any = 0;
        #pragma unroll
        for (int k = 0; k < KNB; k++) {
            int idx = gb * KNB + k;
            int v;
            if (mode == 2)      v = (((const float*)validp)[idx] != 0.0f);
            else if (mode == 1) v = (((const unsigned char*)validp)[idx] != 0);
            else                v = (((const int*)validp)[idx] != 0);
            any |= v;
            s[k] = v ? (score[tid * KNB + k] + ab2) : -10000.0f;
        }
        float m = s[0];
        #pragma unroll
        for (int k = 1; k < KNB; k++) m = fmaxf(m, s[k]);
        float e[KNB], sum = 0.0f;
        #pragma unroll
        for (int k = 0; k < KNB; k++) { e[k] = expf(s[k] - m); sum += e[k]; }
        float inv = 1.0f / sum;
        #pragma unroll
        for (int k = 0; k < KNB; k++) wgt[tid * KNB + k] = e[k] * inv;
        g_anyv[gb] = (unsigned char)any;
    }
    for (int i = tid; i < (COMB * HID) / 4; i += 512)
        ((float4*)w1s)[i] = ((const float4*)val_W1)[i];
    for (int i = tid; i < HID; i += 512) b1s[i] = val_b1[i];
    __syncthreads();

    // --- GEMM2: hbar[b] = sum_k w_k * gelu(combined @ val_W1 + b1) ---
    #pragma unroll 1
    for (int it = 0; it < 2; it++) {
        const int t  = tid + it * 512;
        const int bl = t & 15;
        const int cg = t >> 4;           // 0..63
        const int c0 = cg * 4;
        const int r0 = bl * KNB;
        float4 bias = *(const float4*)&b1s[c0];
        float acc[KNB][4];
        #pragma unroll
        for (int i = 0; i < KNB; i++) {
            acc[i][0] = bias.x; acc[i][1] = bias.y; acc[i][2] = bias.z; acc[i][3] = bias.w;
        }
        for (int kk = 0; kk < COMB; kk++) {
            float4 w = *(const float4*)&w1s[kk * HID + c0];
            const float* cb = &combT[kk * ROWS + r0];
            #pragma unroll
            for (int i = 0; i < KNB; i++) {
                float cv = cb[i];
                acc[i][0] += cv * w.x; acc[i][1] += cv * w.y;
                acc[i][2] += cv * w.z; acc[i][3] += cv * w.w;
            }
        }
        float hb0 = 0.f, hb1 = 0.f, hb2 = 0.f, hb3 = 0.f;
        #pragma unroll
        for (int i = 0; i < KNB; i++) {
            float wk = wgt[r0 + i];
            hb0 += wk * gelu_exact(acc[i][0]);
            hb1 += wk * gelu_exact(acc[i][1]);
            hb2 += wk * gelu_exact(acc[i][2]);
            hb3 += wk * gelu_exact(acc[i][3]);
        }
        float4 o; o.x = hb0; o.y = hb1; o.z = hb2; o.w = hb3;
        *(float4*)&g_hbar[(size_t)(b0 + bl) * HID + c0] = o;
    }
}

// ---------------- output GEMM: out = hbar @ val_W2 + b2 (or fallback) ----------------
// smem: hT [256][132] @0 (33792) | w2s [64][256] @33792 (16384) | b2s @50176 | fbs @50432
#define SMEM_D_FLOATS 50688
#define SMEM_D_BYTES (SMEM_D_FLOATS * 4)
#define TILE_M 128

__global__ void __launch_bounds__(512, 1) out_kernel(
    const float* __restrict__ val_W2,
    const float* __restrict__ val_b2,
    const float* __restrict__ fallback,
    float* __restrict__ out)
{
    extern __shared__ float sm[];
    float* hT  = sm;             // [256][132] hT[kk*132 + r]
    float* w2s = sm + 33792;     // [64][256]
    float* b2s = sm + 50176;
    float* fbs = sm + 50432;

    const int tid = threadIdx.x;
    const int m0 = blockIdx.x * TILE_M;

    for (int i = tid; i < 256; i += 512) { b2s[i] = val_b2[i]; fbs[i] = fallback[i]; }
    for (int i = tid; i < TILE_M * 256; i += 512) {
        int r = i >> 8, c = i & 255;
        hT[c * 132 + r] = g_hbar[(size_t)(m0 + r) * 256 + c];
    }

    const int rg = tid >> 5;        // warp 0..15
    const int lane = tid & 31;
    const int r0 = rg * 8, c0 = lane * 8;

    float acc[8][8];
    #pragma unroll
    for (int i = 0; i < 8; i++)
        #pragma unroll
        for (int j = 0; j < 8; j++) acc[i][j] = 0.0f;

    for (int kc = 0; kc < 4; kc++) {
        __syncthreads();
        for (int i = tid; i < (64 * 256) / 4; i += 512)
            ((float4*)w2s)[i] = ((const float4*)val_W2)[kc * 4096 + i];
        __syncthreads();
        #pragma unroll 4
        for (int k2 = 0; k2 < 64; k2++) {
            int kk = kc * 64 + k2;
            float4 ha = *(const float4*)&hT[kk * 132 + r0];
            float4 hb = *(const float4*)&hT[kk * 132 + r0 + 4];
            float4 wa = *(const float4*)&w2s[k2 * 256 + c0];
            float4 wb = *(const float4*)&w2s[k2 * 256 + c0 + 4];
            float h[8] = {ha.x, ha.y, ha.z, ha.w, hb.x, hb.y, hb.z, hb.w};
            float w[8] = {wa.x, wa.y, wa.z, wa.w, wb.x, wb.y, wb.z, wb.w};
            #pragma unroll
            for (int i = 0; i < 8; i++)
                #pragma unroll
                for (int j = 0; j < 8; j++) acc[i][j] += h[i] * w[j];
        }
    }

    #pragma unroll
    for (int i = 0; i < 8; i++) {
        int row = m0 + r0 + i;
        float4 oa, ob;
        if (g_anyv[row]) {
            oa.x = acc[i][0] + b2s[c0 + 0]; oa.y = acc[i][1] + b2s[c0 + 1];
            oa.z = acc[i][2] + b2s[c0 + 2]; oa.w = acc[i][3] + b2s[c0 + 3];
            ob.x = acc[i][4] + b2s[c0 + 4]; ob.y = acc[i][5] + b2s[c0 + 5];
            ob.z = acc[i][6] + b2s[c0 + 6]; ob.w = acc[i][7] + b2s[c0 + 7];
        } else {
            oa = *(const float4*)&fbs[c0];
            ob = *(const float4*)&fbs[c0 + 4];
        }
        *(float4*)&out[(size_t)row * 256 + c0]     = oa;
        *(float4*)&out[(size_t)row * 256 + c0 + 4] = ob;
    }
}

// ---------------- launch ----------------
extern "C" void kernel_launch(void* const* d_in, const int* in_sizes, int n_in,
                              void* d_out, int out_size)
{
    const int*   res_idx  = (const int*)d_in[0];
    const int*   ss_idx   = (const int*)d_in[1];
    const float* dist     = (const float*)d_in[2];
    const int*   seq_sep  = (const int*)d_in[3];
    const float* angles   = (const float*)d_in[4];
    const void*  validp   = d_in[5];
    const float* res_table = (const float*)d_in[6];
    const float* ss_table  = (const float*)d_in[7];
    const float* cont_W    = (const float*)d_in[8];
    const float* cont_b    = (const float*)d_in[9];
    const float* attn_W1   = (const float*)d_in[10];
    const float* attn_b1   = (const float*)d_in[11];
    const float* attn_W2   = (const float*)d_in[12];
    const float* attn_b2   = (const float*)d_in[13];
    const float* val_W1    = (const float*)d_in[14];
    const float* val_b1    = (const float*)d_in[15];
    const float* val_W2    = (const float*)d_in[16];
    const float* val_b2    = (const float*)d_in[17];
    const float* fallback  = (const float*)d_in[18];
    float* out = (float*)d_out;

    cudaFuncSetAttribute(fused_kernel, cudaFuncAttributeMaxDynamicSharedMemorySize, SMEM_B_BYTES);
    cudaFuncSetAttribute(out_kernel,   cudaFuncAttributeMaxDynamicSharedMemorySize, SMEM_D_BYTES);

    detect_valid_kernel<<<1, 1024>>>((const unsigned int*)validp, (B_TOTAL * KNB) / 4);

    fused_kernel<<<B_TOTAL / TILE_B, 512, SMEM_B_BYTES>>>(
        res_idx, ss_idx, dist, seq_sep, angles, validp,
        res_table, ss_table, cont_W, cont_b,
        attn_W1, attn_b1, attn_W2, attn_b2, val_W1, val_b1);

    out_kernel<<<B_TOTAL / TILE_M, 512, SMEM_D_BYTES>>>(val_W2, val_b2, fallback, out);
}

// round 3
// speedup vs baseline: 1.0687x; 1.0687x over previous
#include <cuda_runtime.h>
#include <math.h>

#define B_TOTAL 131072
#define KNB 5
#define TILE_B 64
#define ROWS (TILE_B * KNB)    // 320
#define COMB 128
#define HID 256
#define AH 128
#define LSTRIDE 1282           // per-lane combL stride (10*128 + 2 pad)

// ---------------- scratch ----------------
__device__ float g_hbarT[(size_t)HID * B_TOTAL];    // [col][b] transposed, 134 MB
__device__ unsigned char g_anyv[B_TOTAL];
__device__ int g_flag_u8, g_flag_f32;

// ---------------- f32x2 helpers ----------------
__device__ __forceinline__ void fma2(unsigned long long& d, unsigned long long a, unsigned long long b) {
    asm("fma.rn.f32x2 %0, %1, %2, %0;" : "+l"(d) : "l"(a), "l"(b));
}
__device__ __forceinline__ unsigned long long pack2(float x, float y) {
    unsigned long long r; asm("mov.b64 %0, {%1, %2};" : "=l"(r) : "f"(x), "f"(y)); return r;
}
__device__ __forceinline__ float2 unpack2(unsigned long long v) {
    float2 r; asm("mov.b64 {%0, %1}, %2;" : "=f"(r.x), "=f"(r.y) : "l"(v)); return r;
}
__device__ __forceinline__ float gelu_exact(float x) {
    return 0.5f * x * (1.0f + erff(x * 0.70710678118654752f));
}

// ---------------- valid-dtype probe (parallel) ----------------
__global__ void reset_flags() { g_flag_u8 = 0; g_flag_f32 = 0; }

__global__ void detect_valid(const unsigned int* __restrict__ v, int n) {
    int f8 = 0, f32 = 0;
    for (int i = blockIdx.x * blockDim.x + threadIdx.x; i < n; i += gridDim.x * blockDim.x) {
        unsigned int w = v[i];
        if (w == 0x3F800000u) f32 = 1;
        else if (w > 1u) f8 = 1;
    }
    if (__syncthreads_or(f8) && threadIdx.x == 0) atomicOr(&g_flag_u8, 1);
    if (__syncthreads_or(f32) && threadIdx.x == 0) atomicOr(&g_flag_f32, 1);
}

// ---------------- smem layout (floats) for fused kernel ----------------
#define SMEM_F_FLOATS 53152
#define SMEM_F_BYTES (SMEM_F_FLOATS * 4)

// One N=128 GEMM pass: acc[5 rowpairs][8 cols] over K=128, weights streamed in
// k-chunks of 32 with in-smem duplication (w,w) so row-paired FMA2 needs no packs.
__device__ __forceinline__ void gemm_pass(
    const float* __restrict__ Wg, int ldW, int colOff,
    const float* __restrict__ bias_s,
    float* __restrict__ wdup,
    const float* __restrict__ combL,
    unsigned long long acc[5][8],
    int tid, int lane, int c0)
{
    #pragma unroll
    for (int c = 0; c < 8; c++) {
        float b = bias_s[c0 + c];
        unsigned long long bp = pack2(b, b);
        #pragma unroll
        for (int rp = 0; rp < 5; rp++) acc[rp][c] = bp;
    }
    const float* cl = combL + lane * LSTRIDE;
    for (int kc = 0; kc < COMB; kc += 32) {
        __syncthreads();
        for (int i = tid; i < 32 * 128; i += 512) {
            int kl = i >> 7, c = i & 127;
            float v = Wg[(size_t)(kc + kl) * ldW + colOff + c];
            *(float2*)&wdup[kl * 256 + 2 * c] = make_float2(v, v);
        }
        __syncthreads();
        #pragma unroll 2
        for (int kl = 0; kl < 32; kl++) {
            const unsigned long long* cb = (const unsigned long long*)(cl + (kc + kl) * 10);
            unsigned long long cv0 = cb[0], cv1 = cb[1], cv2 = cb[2], cv3 = cb[3], cv4 = cb[4];
            const ulonglong2* wp = (const ulonglong2*)(wdup + kl * 256 + 2 * c0);
            ulonglong2 wa = wp[0], wb = wp[1], wc = wp[2], wd = wp[3];
            #pragma unroll
            for (int rp = 0; rp < 5; rp++) {
                unsigned long long cv = (rp == 0) ? cv0 : (rp == 1) ? cv1 : (rp == 2) ? cv2 : (rp == 3) ? cv3 : cv4;
                fma2(acc[rp][0], cv, wa.x); fma2(acc[rp][1], cv, wa.y);
                fma2(acc[rp][2], cv, wb.x); fma2(acc[rp][3], cv, wb.y);
                fma2(acc[rp][4], cv, wc.x); fma2(acc[rp][5], cv, wc.y);
                fma2(acc[rp][6], cv, wd.x); fma2(acc[rp][7], cv, wd.y);
            }
        }
    }
}

__global__ void __launch_bounds__(512, 1) fused_kernel(
    const int* __restrict__ res_idx,
    const int* __restrict__ ss_idx,
    const float* __restrict__ dist,
    const int* __restrict__ seq_sep,
    const float* __restrict__ angles,
    const void* __restrict__ validp,
    const float* __restrict__ res_table,
    const float* __restrict__ ss_table,
    const float* __restrict__ cont_W,
    const float* __restrict__ cont_b,
    const float* __restrict__ attn_W1,
    const float* __restrict__ attn_b1,
    const float* __restrict__ attn_W2,
    const float* __restrict__ attn_b2,
    const float* __restrict__ val_W1,
    const float* __restrict__ val_b1)
{
    extern __shared__ float sm[];
    float* combL   = sm;
    float* wdup    = sm + 41024;
    float* feat    = sm + 49216;
    float* score_s = sm + 51136;
    float* wgt_s   = sm + 51456;
    float* biasA   = sm + 51776;
    float* w2a_s   = sm + 51904;
    float* biasV   = sm + 52032;
    float* cWs     = sm + 52288;
    float* cbs     = sm + 52480;
    int*   ridx    = (int*)(sm + 52512);
    int*   sidx    = (int*)(sm + 52832);

    const int tid  = threadIdx.x;
    const int lane = tid & 31;
    const int warp = tid >> 5;
    const int c0   = warp * 8;       // warp's column base within a 128-wide pass
    const int b0   = blockIdx.x * TILE_B;
    const int gr0  = b0 * KNB;

    // ---- stage small constants + per-row features ----
    for (int i = tid; i < 192; i += 512) cWs[i] = cont_W[i];
    if (tid < 32) cbs[tid] = cont_b[tid];
    if (tid < AH) { biasA[tid] = attn_b1[tid]; w2a_s[tid] = attn_W2[tid]; }
    for (int i = tid; i < HID; i += 512) biasV[i] = val_b1[i];
    if (tid < ROWS) {
        int gr = gr0 + tid;
        ridx[tid] = res_idx[gr];
        sidx[tid] = ss_idx[gr];
        float d = dist[gr];
        if (d != d) d = 0.0f;
        feat[tid * 6 + 0] = d * (1.0f / 15.0f);
        feat[tid * 6 + 1] = log1pf(fabsf((float)seq_sep[gr])) * 0.2f;
        float4 a = ((const float4*)angles)[gr];
        feat[tid * 6 + 2] = (a.x != a.x) ? 0.0f : a.x;
        feat[tid * 6 + 3] = (a.y != a.y) ? 0.0f : a.y;
        feat[tid * 6 + 4] = (a.z != a.z) ? 0.0f : a.z;
        feat[tid * 6 + 5] = (a.w != a.w) ? 0.0f : a.w;
        score_s[tid] = 0.0f;
    }
    __syncthreads();

    // ---- build combL: per-lane layout combL[lane][k][rowj] ----
    // row r (0..319) -> lane r/10, slot r%10; feature k 0..127
    for (int i = tid; i < ROWS * 64; i += 512) {
        int r = i >> 6, c = i & 63;
        combL[(r / 10) * LSTRIDE + c * 10 + (r % 10)] = res_table[ridx[r] * 64 + c];
    }
    for (int i = tid; i < ROWS * 32; i += 512) {
        int r = i >> 5, c = i & 31;
        combL[(r / 10) * LSTRIDE + (64 + c) * 10 + (r % 10)] = ss_table[sidx[r] * 32 + c];
    }
    for (int i = tid; i < ROWS * 32; i += 512) {
        int r = i >> 5, c = i & 31;
        float s = cbs[c];
        #pragma unroll
        for (int j = 0; j < 6; j++) s += feat[r * 6 + j] * cWs[j * 32 + c];
        combL[(r / 10) * LSTRIDE + (96 + c) * 10 + (r % 10)] = s;
    }
    __syncthreads();

    unsigned long long acc[5][8];

    // ---- GEMM1: attention scores ----
    gemm_pass(attn_W1, AH, 0, biasA, wdup, combL, acc, tid, lane, c0);
    {
        float w2v[8];
        #pragma unroll
        for (int c = 0; c < 8; c++) w2v[c] = w2a_s[c0 + c];
        #pragma unroll
        for (int rp = 0; rp < 5; rp++) {
            float p0 = 0.0f, p1 = 0.0f;
            #pragma unroll
            for (int c = 0; c < 8; c++) {
                float2 f = unpack2(acc[rp][c]);
                p0 += gelu_exact(f.x) * w2v[c];
                p1 += gelu_exact(f.y) * w2v[c];
            }
            atomicAdd(&score_s[lane * 10 + 2 * rp], p0);
            atomicAdd(&score_s[lane * 10 + 2 * rp + 1], p1);
        }
    }
    __syncthreads();

    // ---- softmax + validity (threads 0..63) ----
    if (tid < TILE_B) {
        int gb = b0 + tid;
        float ab2 = attn_b2[0];
        int fu8 = g_flag_u8, ff32 = g_flag_f32;
        float s[KNB];
        int any = 0;
        #pragma unroll
        for (int k = 0; k < KNB; k++) {
            int idx = gb * KNB + k;
            int v;
            if (ff32)      v = (((const float*)validp)[idx] != 0.0f);
            else if (fu8)  v = (((const unsigned char*)validp)[idx] != 0);
            else           v = (((const int*)validp)[idx] != 0);
            any |= v;
            s[k] = v ? (score_s[tid * KNB + k] + ab2) : -10000.0f;
        }
        float m = s[0];
        #pragma unroll
        for (int k = 1; k < KNB; k++) m = fmaxf(m, s[k]);
        float e[KNB], sum = 0.0f;
        #pragma unroll
        for (int k = 0; k < KNB; k++) { e[k] = expf(s[k] - m); sum += e[k]; }
        float inv = 1.0f / sum;
        #pragma unroll
        for (int k = 0; k < KNB; k++) wgt_s[tid * KNB + k] = e[k] * inv;
        g_anyv[gb] = (unsigned char)any;
    }
    __syncthreads();

    // ---- GEMM2: value MLP layer 1, weighted-sum to hbarT (two 128-col halves) ----
    #pragma unroll 1
    for (int half = 0; half < 2; half++) {
        gemm_pass(val_W1, HID, half * 128, biasV + half * 128, wdup, combL, acc, tid, lane, c0);
        float hbA[8], hbB[8];
        #pragma unroll
        for (int c = 0; c < 8; c++) { hbA[c] = 0.0f; hbB[c] = 0.0f; }
        #pragma unroll
        for (int rp = 0; rp < 5; rp++) {
            float wk0 = wgt_s[lane * 10 + 2 * rp];
            float wk1 = wgt_s[lane * 10 + 2 * rp + 1];
            #pragma unroll
            for (int c = 0; c < 8; c++) {
                float2 f = unpack2(acc[rp][c]);
                float g0 = wk0 * gelu_exact(f.x);
                float g1 = wk1 * gelu_exact(f.y);
                if (2 * rp < 5)     hbA[c] += g0; else hbB[c] += g0;
                if (2 * rp + 1 < 5) hbA[c] += g1; else hbB[c] += g1;
            }
        }
        int bA = b0 + lane * 2;
        int colb = half * 128 + c0;
        #pragma unroll
        for (int c = 0; c < 8; c++) {
            *(float2*)(g_hbarT + (size_t)(colb + c) * B_TOTAL + bA) = make_float2(hbA[c], hbB[c]);
        }
    }
}

// ---------------- output GEMM: out = hbarT^T @ val_W2 + b2 (or fallback) ----------------
// smem: hT [256][132] @0 (33792) | wdup [16][512] @33792 (8192) | b2s @41984 | fbs @42240
#define SMEM_O_FLOATS 42496
#define SMEM_O_BYTES (SMEM_O_FLOATS * 4)
#define TILE_M 128

__global__ void __launch_bounds__(512, 1) out_kernel(
    const float* __restrict__ val_W2,
    const float* __restrict__ val_b2,
    const float* __restrict__ fallback,
    float* __restrict__ out)
{
    extern __shared__ float sm[];
    float* hT   = sm;            // hT[k*132 + r]
    float* wdup = sm + 33792;    // [16][512] duplicated
    float* b2s  = sm + 41984;
    float* fbs  = sm + 42240;

    const int tid  = threadIdx.x;
    const int lane = tid & 31;
    const int warp = tid >> 5;
    const int c0   = warp * 16;
    const int m0   = blockIdx.x * TILE_M;

    for (int i = tid; i < HID; i += 512) { b2s[i] = val_b2[i]; fbs[i] = fallback[i]; }
    // stage hT from transposed hbar: coalesced float4 reads, conflict-free float4 stores
    for (int i = tid; i < HID * (TILE_M / 4); i += 512) {
        int k = i >> 5, q = i & 31;
        float4 v = *(const float4*)(g_hbarT + (size_t)k * B_TOTAL + m0 + q * 4);
        *(float4*)(hT + k * 132 + q * 4) = v;
    }

    unsigned long long acc[2][16];
    #pragma unroll
    for (int rp = 0; rp < 2; rp++)
        #pragma unroll
        for (int c = 0; c < 16; c++) acc[rp][c] = 0ull;

    for (int kc = 0; kc < HID; kc += 16) {
        __syncthreads();
        for (int i = tid; i < 16 * 256; i += 512) {
            int kl = i >> 8, c = i & 255;
            float v = val_W2[(size_t)(kc + kl) * 256 + c];
            *(float2*)&wdup[kl * 512 + 2 * c] = make_float2(v, v);
        }
        __syncthreads();
        #pragma unroll 4
        for (int kl = 0; kl < 16; kl++) {
            ulonglong2 cb = *(const ulonglong2*)(hT + (kc + kl) * 132 + lane * 4);
            const ulonglong2* wp = (const ulonglong2*)(wdup + kl * 512 + 2 * c0);
            #pragma unroll
            for (int cc = 0; cc < 8; cc++) {
                ulonglong2 w2 = wp[cc];
                fma2(acc[0][2 * cc],     cb.x, w2.x);
                fma2(acc[0][2 * cc + 1], cb.x, w2.y);
                fma2(acc[1][2 * cc],     cb.y, w2.x);
                fma2(acc[1][2 * cc + 1], cb.y, w2.y);
            }
        }
    }

    // epilogue: 4 rows per lane (lane*4 + 2*rp + h)
    #pragma unroll
    for (int rp = 0; rp < 2; rp++) {
        #pragma unroll
        for (int h = 0; h < 2; h++) {
            int row = m0 + lane * 4 + 2 * rp + h;
            int av = g_anyv[row];
            float o[16];
            #pragma unroll
            for (int c = 0; c < 16; c++) {
                float2 f = unpack2(acc[rp][c]);
                float v = h ? f.y : f.x;
                o[c] = av ? (v + b2s[c0 + c]) : fbs[c0 + c];
            }
            #pragma unroll
            for (int q = 0; q < 4; q++) {
                *(float4*)(out + (size_t)row * 256 + c0 + q * 4) =
                    make_float4(o[q * 4], o[q * 4 + 1], o[q * 4 + 2], o[q * 4 + 3]);
            }
        }
    }
}

// ---------------- launch ----------------
extern "C" void kernel_launch(void* const* d_in, const int* in_sizes, int n_in,
                              void* d_out, int out_size)
{
    const int*   res_idx   = (const int*)d_in[0];
    const int*   ss_idx    = (const int*)d_in[1];
    const float* dist      = (const float*)d_in[2];
    const int*   seq_sep   = (const int*)d_in[3];
    const float* angles    = (const float*)d_in[4];
    const void*  validp    = d_in[5];
    const float* res_table = (const float*)d_in[6];
    const float* ss_table  = (const float*)d_in[7];
    const float* cont_W    = (const float*)d_in[8];
    const float* cont_b    = (const float*)d_in[9];
    const float* attn_W1   = (const float*)d_in[10];
    const float* attn_b1   = (const float*)d_in[11];
    const float* attn_W2   = (const float*)d_in[12];
    const float* attn_b2   = (const float*)d_in[13];
    const float* val_W1    = (const float*)d_in[14];
    const float* val_b1    = (const float*)d_in[15];
    const float* val_W2    = (const float*)d_in[16];
    const float* val_b2    = (const float*)d_in[17];
    const float* fallback  = (const float*)d_in[18];
    float* out = (float*)d_out;

    cudaFuncSetAttribute(fused_kernel, cudaFuncAttributeMaxDynamicSharedMemorySize, SMEM_F_BYTES);
    cudaFuncSetAttribute(out_kernel,   cudaFuncAttributeMaxDynamicSharedMemorySize, SMEM_O_BYTES);

    reset_flags<<<1, 1>>>();
    detect_valid<<<148, 1024>>>((const unsigned int*)validp, (B_TOTAL * KNB) / 4);

    fused_kernel<<<B_TOTAL / TILE_B, 512, SMEM_F_BYTES>>>(
        res_idx, ss_idx, dist, seq_sep, angles, validp,
        res_table, ss_table, cont_W, cont_b,
        attn_W1, attn_b1, attn_W2, attn_b2, val_W1, val_b1);

    out_kernel<<<B_TOTAL / TILE_M, 512, SMEM_O_BYTES>>>(val_W2, val_b2, fallback, out);
}

// round 4
// speedup vs baseline: 1.5390x; 1.4401x over previous
#include <cuda_runtime.h>
#include <math.h>

#define B_TOTAL 131072
#define KNB 5
#define TILE_B 32
#define ROWSF (TILE_B * KNB)   // 160
#define COMB 128
#define HID 256
#define AH 128
#define CLD 132                // smem leading dim (bank-spread: (4g+t) pattern)

typedef unsigned int uint32;

// ---------------- scratch ----------------
__device__ float g_hbar[(size_t)B_TOTAL * HID];   // [b][256] fp32, 134 MB
__device__ unsigned char g_anyv[B_TOTAL];
__device__ int g_flag_u8, g_flag_f32;

// ---------------- helpers ----------------
__device__ __forceinline__ uint32 f2tf(float f) {
    uint32 r; asm("cvt.rna.tf32.f32 %0, %1;" : "=r"(r) : "f"(f)); return r;
}
__device__ __forceinline__ void mma_tf32(float d[4], const uint32 a[4], const uint32 b[2]) {
    asm("mma.sync.aligned.m16n8k8.row.col.f32.tf32.tf32.f32 "
        "{%0,%1,%2,%3}, {%4,%5,%6,%7}, {%8,%9}, {%0,%1,%2,%3};"
        : "+f"(d[0]), "+f"(d[1]), "+f"(d[2]), "+f"(d[3])
        : "r"(a[0]), "r"(a[1]), "r"(a[2]), "r"(a[3]), "r"(b[0]), "r"(b[1]));
}
__device__ __forceinline__ float gelu_exact(float x) {
    return 0.5f * x * (1.0f + erff(x * 0.70710678118654752f));
}

// ---------------- valid-dtype probe ----------------
__global__ void reset_flags() { g_flag_u8 = 0; g_flag_f32 = 0; }

__global__ void detect_valid(const unsigned int* __restrict__ v, int n) {
    int f8 = 0, f32 = 0;
    for (int i = blockIdx.x * blockDim.x + threadIdx.x; i < n; i += gridDim.x * blockDim.x) {
        unsigned int w = v[i];
        if (w == 0x3F800000u) f32 = 1;
        else if (w > 1u) f8 = 1;
    }
    if (__syncthreads_or(f8) && threadIdx.x == 0) atomicOr(&g_flag_u8, 1);
    if (__syncthreads_or(f32) && threadIdx.x == 0) atomicOr(&g_flag_f32, 1);
}

// ---------------- fused kernel smem layout (floats) ----------------
// comb  @0     : 160*132 = 21120  (tf32 bits)
// Ws    @21120 : 128*132 = 16896  (tf32 bits, B[n][k])
// hbar  @38016 : 32*260  = 8320
// feat  @46336 : 960
// score @47296 : 160
// wgt   @47456 : 160
// biasA @47616 : 128
// w2a   @47744 : 128
// biasV @47872 : 256
// cWs   @48128 : 192
// cbs   @48320 : 32
// ridx  @48352 : 160 (int)
// sidx  @48512 : 160 (int)
#define SMEM_F_FLOATS 48672
#define SMEM_F_BYTES (SMEM_F_FLOATS * 4)

__global__ void __launch_bounds__(512, 1) fused_kernel(
    const int* __restrict__ res_idx,
    const int* __restrict__ ss_idx,
    const float* __restrict__ dist,
    const int* __restrict__ seq_sep,
    const float* __restrict__ angles,
    const void* __restrict__ validp,
    const float* __restrict__ res_table,
    const float* __restrict__ ss_table,
    const float* __restrict__ cont_W,
    const float* __restrict__ cont_b,
    const float* __restrict__ attn_W1,
    const float* __restrict__ attn_b1,
    const float* __restrict__ attn_W2,
    const float* __restrict__ attn_b2,
    const float* __restrict__ val_W1,
    const float* __restrict__ val_b1)
{
    extern __shared__ float sm[];
    float* comb   = sm;
    float* Ws     = sm + 21120;
    float* hbar_s = sm + 38016;
    float* feat   = sm + 46336;
    float* score_s= sm + 47296;
    float* wgt_s  = sm + 47456;
    float* biasA  = sm + 47616;
    float* w2a_s  = sm + 47744;
    float* biasV  = sm + 47872;
    float* cWs    = sm + 48128;
    float* cbs    = sm + 48320;
    int*   ridx   = (int*)(sm + 48352);
    int*   sidx   = (int*)(sm + 48512);

    const int tid  = threadIdx.x;
    const int lane = tid & 31;
    const int warp = tid >> 5;
    const int g    = lane >> 2;     // 0..7
    const int t    = lane & 3;      // 0..3
    const int wm   = warp >> 3;     // 0..1  (M groups of 80 rows)
    const int wn   = warp & 7;      // 0..7  (N groups of 16 cols)
    const int b0   = blockIdx.x * TILE_B;
    const int gr0  = b0 * KNB;

    const uint32* combu = (const uint32*)comb;
    const uint32* wsu   = (const uint32*)Ws;

    // ---------- phase 0: constants, features, zero init ----------
    for (int i = tid; i < 192; i += 512) cWs[i] = cont_W[i];
    if (tid < 32) cbs[tid] = cont_b[tid];
    if (tid < AH) { biasA[tid] = attn_b1[tid]; w2a_s[tid] = attn_W2[tid]; }
    for (int i = tid; i < HID; i += 512) biasV[i] = val_b1[i];
    for (int i = tid; i < 32 * 260; i += 512) hbar_s[i] = 0.0f;
    if (tid < ROWSF) {
        int gr = gr0 + tid;
        ridx[tid] = res_idx[gr];
        sidx[tid] = ss_idx[gr];
        float d = dist[gr];
        if (d != d) d = 0.0f;
        feat[tid * 6 + 0] = d * (1.0f / 15.0f);
        feat[tid * 6 + 1] = log1pf(fabsf((float)seq_sep[gr])) * 0.2f;
        float4 a = ((const float4*)angles)[gr];
        feat[tid * 6 + 2] = (a.x != a.x) ? 0.0f : a.x;
        feat[tid * 6 + 3] = (a.y != a.y) ? 0.0f : a.y;
        feat[tid * 6 + 4] = (a.z != a.z) ? 0.0f : a.z;
        feat[tid * 6 + 5] = (a.w != a.w) ? 0.0f : a.w;
        score_s[tid] = 0.0f;
    }
    __syncthreads();

    // ---------- phase 1: build comb (tf32) + stage attn_W1^T (tf32) ----------
    for (int i = tid; i < ROWSF * 64; i += 512) {
        int r = i >> 6, c = i & 63;
        comb[r * CLD + c] = __uint_as_float(f2tf(res_table[ridx[r] * 64 + c]));
    }
    for (int i = tid; i < ROWSF * 32; i += 512) {
        int r = i >> 5, c = i & 31;
        comb[r * CLD + 64 + c] = __uint_as_float(f2tf(ss_table[sidx[r] * 32 + c]));
    }
    for (int i = tid; i < ROWSF * 32; i += 512) {
        int r = i >> 5, c = i & 31;
        float s = cbs[c];
        #pragma unroll
        for (int j = 0; j < 6; j++) s += feat[r * 6 + j] * cWs[j * 32 + c];
        comb[r * CLD + 96 + c] = __uint_as_float(f2tf(s));
    }
    for (int i = tid; i < AH * COMB; i += 512) {
        int k = i >> 7, n = i & 127;
        Ws[n * CLD + k] = __uint_as_float(f2tf(attn_W1[k * AH + n]));
    }
    __syncthreads();

    // ---------- phase 2: GEMM1 (scores) ----------
    {
        float acc[5][2][4];
        #pragma unroll
        for (int mi = 0; mi < 5; mi++)
            #pragma unroll
            for (int ni = 0; ni < 2; ni++)
                #pragma unroll
                for (int q = 0; q < 4; q++) acc[mi][ni][q] = 0.0f;

        const int mrow0 = wm * 80 + g;
        const int nb = wn * 16;
        #pragma unroll 2
        for (int ks = 0; ks < 16; ks++) {
            int kb = ks * 8;
            uint32 a[5][4];
            #pragma unroll
            for (int mi = 0; mi < 5; mi++) {
                const uint32* base = combu + (mrow0 + mi * 16) * CLD + kb + t;
                a[mi][0] = base[0];
                a[mi][1] = base[8 * CLD];
                a[mi][2] = base[4];
                a[mi][3] = base[8 * CLD + 4];
            }
            uint32 bb[2][2];
            #pragma unroll
            for (int ni = 0; ni < 2; ni++) {
                const uint32* bp = wsu + (nb + ni * 8 + g) * CLD + kb + t;
                bb[ni][0] = bp[0];
                bb[ni][1] = bp[4];
            }
            #pragma unroll
            for (int mi = 0; mi < 5; mi++)
                #pragma unroll
                for (int ni = 0; ni < 2; ni++)
                    mma_tf32(acc[mi][ni], a[mi], bb[ni]);
        }
        // epilogue: p = sum_cols gelu(d + biasA) * w2a ; reduce over t ; atomic per row
        #pragma unroll
        for (int mi = 0; mi < 5; mi++) {
            #pragma unroll
            for (int rh = 0; rh < 2; rh++) {
                int r = wm * 80 + mi * 16 + g + 8 * rh;
                float p = 0.0f;
                #pragma unroll
                for (int ni = 0; ni < 2; ni++) {
                    #pragma unroll
                    for (int c = 0; c < 2; c++) {
                        int col = nb + ni * 8 + 2 * t + c;
                        float d = acc[mi][ni][rh * 2 + c];
                        p += gelu_exact(d + biasA[col]) * w2a_s[col];
                    }
                }
                p += __shfl_xor_sync(0xFFFFFFFFu, p, 1);
                p += __shfl_xor_sync(0xFFFFFFFFu, p, 2);
                if (t == 0) atomicAdd(&score_s[r], p);
            }
        }
    }
    __syncthreads();

    // ---------- phase 3: softmax (tid<32) + stage val_W1 half0 ----------
    if (tid < TILE_B) {
        int gb = b0 + tid;
        float ab2 = attn_b2[0];
        int fu8 = g_flag_u8, ff32 = g_flag_f32;
        float s[KNB];
        int any = 0;
        #pragma unroll
        for (int k = 0; k < KNB; k++) {
            int idx = gb * KNB + k;
            int v;
            if (ff32)      v = (((const float*)validp)[idx] != 0.0f);
            else if (fu8)  v = (((const unsigned char*)validp)[idx] != 0);
            else           v = (((const int*)validp)[idx] != 0);
            any |= v;
            s[k] = v ? (score_s[tid * KNB + k] + ab2) : -10000.0f;
        }
        float m = s[0];
        #pragma unroll
        for (int k = 1; k < KNB; k++) m = fmaxf(m, s[k]);
        float e[KNB], sum = 0.0f;
        #pragma unroll
        for (int k = 0; k < KNB; k++) { e[k] = expf(s[k] - m); sum += e[k]; }
        float inv = 1.0f / sum;
        #pragma unroll
        for (int k = 0; k < KNB; k++) wgt_s[tid * KNB + k] = e[k] * inv;
        g_anyv[gb] = (unsigned char)any;
    }
    for (int i = tid; i < 128 * COMB; i += 512) {
        int k = i >> 7, n = i & 127;
        Ws[n * CLD + k] = __uint_as_float(f2tf(val_W1[k * HID + n]));
    }
    __syncthreads();

    // ---------- phases 4-6: GEMM2 halves ----------
    #pragma unroll 1
    for (int half = 0; half < 2; half++) {
        if (half == 1) {
            // restage second half of val_W1
            for (int i = tid; i < 128 * COMB; i += 512) {
                int k = i >> 7, n = i & 127;
                Ws[n * CLD + k] = __uint_as_float(f2tf(val_W1[k * HID + 128 + n]));
            }
            __syncthreads();
        }
        float acc[5][2][4];
        #pragma unroll
        for (int mi = 0; mi < 5; mi++)
            #pragma unroll
            for (int ni = 0; ni < 2; ni++)
                #pragma unroll
                for (int q = 0; q < 4; q++) acc[mi][ni][q] = 0.0f;

        const int mrow0 = wm * 80 + g;
        const int nb = wn * 16;
        #pragma unroll 2
        for (int ks = 0; ks < 16; ks++) {
            int kb = ks * 8;
            uint32 a[5][4];
            #pragma unroll
            for (int mi = 0; mi < 5; mi++) {
                const uint32* base = combu + (mrow0 + mi * 16) * CLD + kb + t;
                a[mi][0] = base[0];
                a[mi][1] = base[8 * CLD];
                a[mi][2] = base[4];
                a[mi][3] = base[8 * CLD + 4];
            }
            uint32 bb[2][2];
            #pragma unroll
            for (int ni = 0; ni < 2; ni++) {
                const uint32* bp = wsu + (nb + ni * 8 + g) * CLD + kb + t;
                bb[ni][0] = bp[0];
                bb[ni][1] = bp[4];
            }
            #pragma unroll
            for (int mi = 0; mi < 5; mi++)
                #pragma unroll
                for (int ni = 0; ni < 2; ni++)
                    mma_tf32(acc[mi][ni], a[mi], bb[ni]);
        }
        // epilogue: hbar[b][col] += wgt[row] * gelu(d + biasV)
        #pragma unroll
        for (int mi = 0; mi < 5; mi++) {
            #pragma unroll
            for (int rh = 0; rh < 2; rh++) {
                int r = wm * 80 + mi * 16 + g + 8 * rh;
                float wk = wgt_s[r];
                int bl = r / KNB;
                #pragma unroll
                for (int ni = 0; ni < 2; ni++) {
                    #pragma unroll
                    for (int c = 0; c < 2; c++) {
                        int col = nb + ni * 8 + 2 * t + c;
                        float d = acc[mi][ni][rh * 2 + c];
                        float v = wk * gelu_exact(d + biasV[half * 128 + col]);
                        atomicAdd(&hbar_s[bl * 260 + half * 128 + col], v);
                    }
                }
            }
        }
        __syncthreads();
    }

    // ---------- phase 7: write hbar to gmem ----------
    for (int i = tid; i < TILE_B * HID / 4; i += 512) {
        int r = i >> 6, q = i & 63;
        float4 v = *(const float4*)&hbar_s[r * 260 + q * 4];
        *(float4*)&g_hbar[(size_t)(b0 + r) * HID + q * 4] = v;
    }
}

// ---------------- out kernel: out = hbar @ val_W2 + b2 (or fallback) ----------------
// smem: A @0: 128*132=16896 | Ws @16896: 256*132=33792 | b2s @50688 | fbs @50944
#define SMEM_O_FLOATS 51200
#define SMEM_O_BYTES (SMEM_O_FLOATS * 4)
#define TILE_M 128

__global__ void __launch_bounds__(512, 1) out_kernel(
    const float* __restrict__ val_W2,
    const float* __restrict__ val_b2,
    const float* __restrict__ fallback,
    float* __restrict__ out)
{
    extern __shared__ float sm[];
    float* As  = sm;            // A[r][k] tf32
    float* Ws  = sm + 16896;    // B[n][k] tf32
    float* b2s = sm + 50688;
    float* fbs = sm + 50944;

    const int tid  = threadIdx.x;
    const int lane = tid & 31;
    const int warp = tid >> 5;
    const int g    = lane >> 2;
    const int t    = lane & 3;
    const int wm   = warp >> 2;   // 0..3 (32 rows each)
    const int wn   = warp & 3;    // 0..3 (64 cols each)
    const int m0   = blockIdx.x * TILE_M;

    const uint32* au = (const uint32*)As;
    const uint32* wu = (const uint32*)Ws;

    for (int i = tid; i < HID; i += 512) { b2s[i] = val_b2[i]; fbs[i] = fallback[i]; }

    float acc[2][8][4];
    #pragma unroll
    for (int mi = 0; mi < 2; mi++)
        #pragma unroll
        for (int ni = 0; ni < 8; ni++)
            #pragma unroll
            for (int q = 0; q < 4; q++) acc[mi][ni][q] = 0.0f;

    #pragma unroll 1
    for (int kc = 0; kc < HID; kc += 128) {
        __syncthreads();
        // stage A chunk [128 rows][128 k]
        for (int i = tid; i < TILE_M * 128; i += 512) {
            int r = i >> 7, kk = i & 127;
            As[r * CLD + kk] = __uint_as_float(f2tf(g_hbar[(size_t)(m0 + r) * HID + kc + kk]));
        }
        // stage B chunk [256 n][128 k] (transpose of val_W2[k][n])
        for (int i = tid; i < HID * 128; i += 512) {
            int kk = i >> 8, n = i & 255;
            Ws[n * CLD + kk] = __uint_as_float(f2tf(val_W2[(size_t)(kc + kk) * HID + n]));
        }
        __syncthreads();
        #pragma unroll 2
        for (int ks = 0; ks < 16; ks++) {
            int kb = ks * 8;
            uint32 a[2][4];
            #pragma unroll
            for (int mi = 0; mi < 2; mi++) {
                const uint32* base = au + (wm * 32 + mi * 16 + g) * CLD + kb + t;
                a[mi][0] = base[0];
                a[mi][1] = base[8 * CLD];
                a[mi][2] = base[4];
                a[mi][3] = base[8 * CLD + 4];
            }
            uint32 bb[8][2];
            #pragma unroll
            for (int ni = 0; ni < 8; ni++) {
                const uint32* bp = wu + (wn * 64 + ni * 8 + g) * CLD + kb + t;
                bb[ni][0] = bp[0];
                bb[ni][1] = bp[4];
            }
            #pragma unroll
            for (int mi = 0; mi < 2; mi++)
                #pragma unroll
                for (int ni = 0; ni < 8; ni++)
                    mma_tf32(acc[mi][ni], a[mi], bb[ni]);
        }
    }

    // epilogue
    #pragma unroll
    for (int mi = 0; mi < 2; mi++) {
        #pragma unroll
        for (int rh = 0; rh < 2; rh++) {
            int row = m0 + wm * 32 + mi * 16 + g + 8 * rh;
            int av = g_anyv[row];
            #pragma unroll
            for (int ni = 0; ni < 8; ni++) {
                int colb = wn * 64 + ni * 8 + 2 * t;
                float x0 = acc[mi][ni][rh * 2 + 0];
                float x1 = acc[mi][ni][rh * 2 + 1];
                float2 o;
                if (av) { o.x = x0 + b2s[colb]; o.y = x1 + b2s[colb + 1]; }
                else    { o.x = fbs[colb];      o.y = fbs[colb + 1]; }
                *(float2*)(out + (size_t)row * HID + colb) = o;
            }
        }
    }
}

// ---------------- launch ----------------
extern "C" void kernel_launch(void* const* d_in, const int* in_sizes, int n_in,
                              void* d_out, int out_size)
{
    const int*   res_idx   = (const int*)d_in[0];
    const int*   ss_idx    = (const int*)d_in[1];
    const float* dist      = (const float*)d_in[2];
    const int*   seq_sep   = (const int*)d_in[3];
    const float* angles    = (const float*)d_in[4];
    const void*  validp    = d_in[5];
    const float* res_table = (const float*)d_in[6];
    const float* ss_table  = (const float*)d_in[7];
    const float* cont_W    = (const float*)d_in[8];
    const float* cont_b    = (const float*)d_in[9];
    const float* attn_W1   = (const float*)d_in[10];
    const float* attn_b1   = (const float*)d_in[11];
    const float* attn_W2   = (const float*)d_in[12];
    const float* attn_b2   = (const float*)d_in[13];
    const float* val_W1    = (const float*)d_in[14];
    const float* val_b1    = (const float*)d_in[15];
    const float* val_W2    = (const float*)d_in[16];
    const float* val_b2    = (const float*)d_in[17];
    const float* fallback  = (const float*)d_in[18];
    float* out = (float*)d_out;

    cudaFuncSetAttribute(fused_kernel, cudaFuncAttributeMaxDynamicSharedMemorySize, SMEM_F_BYTES);
    cudaFuncSetAttribute(out_kernel,   cudaFuncAttributeMaxDynamicSharedMemorySize, SMEM_O_BYTES);

    reset_flags<<<1, 1>>>();
    detect_valid<<<148, 1024>>>((const unsigned int*)validp, (B_TOTAL * KNB) / 4);

    fused_kernel<<<B_TOTAL / TILE_B, 512, SMEM_F_BYTES>>>(
        res_idx, ss_idx, dist, seq_sep, angles, validp,
        res_table, ss_table, cont_W, cont_b,
        attn_W1, attn_b1, attn_W2, attn_b2, val_W1, val_b1);

    out_kernel<<<B_TOTAL / TILE_M, 512, SMEM_O_BYTES>>>(val_W2, val_b2, fallback, out);
}

// round 5
// speedup vs baseline: 2.0977x; 1.3630x over previous
#include <cuda_runtime.h>
#include <math.h>

#define B_TOTAL 131072
#define KNB 5
#define TILE_B 32
#define ROWSF (TILE_B * KNB)   // 160
#define COMB 128
#define HID 256
#define AH 128
#define CLD 132                // smem leading dim

typedef unsigned int uint32;

// ---------------- scratch ----------------
__device__ float g_hbar[(size_t)B_TOTAL * HID];   // [b][256] fp32, 134 MB
__device__ unsigned char g_anyv[B_TOTAL];
__device__ int g_flag_u8, g_flag_f32;

// ---------------- helpers ----------------
__device__ __forceinline__ uint32 f2tf(float f) {
    uint32 r; asm("cvt.rna.tf32.f32 %0, %1;" : "=r"(r) : "f"(f)); return r;
}
__device__ __forceinline__ void mma_tf32(float d[4], const uint32 a[4], const uint32 b[2]) {
    asm("mma.sync.aligned.m16n8k8.row.col.f32.tf32.tf32.f32 "
        "{%0,%1,%2,%3}, {%4,%5,%6,%7}, {%8,%9}, {%0,%1,%2,%3};"
        : "+f"(d[0]), "+f"(d[1]), "+f"(d[2]), "+f"(d[3])
        : "r"(a[0]), "r"(a[1]), "r"(a[2]), "r"(a[3]), "r"(b[0]), "r"(b[1]));
}
__device__ __forceinline__ float gelu_exact(float x) {
    return 0.5f * x * (1.0f + erff(x * 0.70710678118654752f));
}

// ---------------- valid-dtype probe ----------------
__global__ void reset_flags() { g_flag_u8 = 0; g_flag_f32 = 0; }

__global__ void detect_valid(const unsigned int* __restrict__ v, int n) {
    int f8 = 0, f32 = 0;
    for (int i = blockIdx.x * blockDim.x + threadIdx.x; i < n; i += gridDim.x * blockDim.x) {
        unsigned int w = v[i];
        if (w == 0x3F800000u) f32 = 1;
        else if (w > 1u) f8 = 1;
    }
    if (__syncthreads_or(f8) && threadIdx.x == 0) atomicOr(&g_flag_u8, 1);
    if (__syncthreads_or(f32) && threadIdx.x == 0) atomicOr(&g_flag_f32, 1);
}

// ---------------- fused kernel smem layout (floats) ----------------
// comb @0: 21120 | Ws @21120: 16896 | hbar @38016: 8320 | P @46336: 8320
// feat @54656: 960 | score @55616: 160 | wgt @55776: 160 | biasA @55936: 128
// w2a @56064: 128 | biasV @56192: 256 | cWs @56448: 192 | cbs @56640: 32
// ridx @56672: 160 | sidx @56832: 160   -> total 56992 floats = 227968 B
#define SMEM_F_BYTES 227968

__global__ void __launch_bounds__(512, 1) fused_kernel(
    const int* __restrict__ res_idx,
    const int* __restrict__ ss_idx,
    const float* __restrict__ dist,
    const int* __restrict__ seq_sep,
    const float* __restrict__ angles,
    const void* __restrict__ validp,
    const float* __restrict__ res_table,
    const float* __restrict__ ss_table,
    const float* __restrict__ cont_W,
    const float* __restrict__ cont_b,
    const float* __restrict__ attn_W1,
    const float* __restrict__ attn_b1,
    const float* __restrict__ attn_W2,
    const float* __restrict__ attn_b2,
    const float* __restrict__ val_W1,
    const float* __restrict__ val_b1)
{
    extern __shared__ float sm[];
    float* comb    = sm;
    float* Ws      = sm + 21120;
    float* hbar_s  = sm + 38016;
    float* P       = sm + 46336;   // pA=P, pB=P+4160; also part_s for GEMM1
    float* feat    = sm + 54656;
    float* score_s = sm + 55616;
    float* wgt_s   = sm + 55776;
    float* biasA   = sm + 55936;
    float* w2a_s   = sm + 56064;
    float* biasV   = sm + 56192;
    float* cWs     = sm + 56448;
    float* cbs     = sm + 56640;
    int*   ridx    = (int*)(sm + 56672);
    int*   sidx    = (int*)(sm + 56832);

    const int tid  = threadIdx.x;
    const int lane = tid & 31;
    const int warp = tid >> 5;
    const int g    = lane >> 2;     // 0..7
    const int t    = lane & 3;      // 0..3
    const int wm   = warp >> 3;     // 0..1 (M half: rows wm*80..wm*80+79)
    const int wn   = warp & 7;      // 0..7 (16 cols each)
    const int nb   = wn * 16;
    const int mrow0 = wm * 80 + g;
    const int b0   = blockIdx.x * TILE_B;
    const int gr0  = b0 * KNB;

    const uint32* combu = (const uint32*)comb;
    const uint32* wsu   = (const uint32*)Ws;

    // ---------- phase 0: constants + per-row features (natural order j=b*5+k) ----------
    for (int i = tid; i < 192; i += 512) cWs[i] = cont_W[i];
    if (tid < 32) cbs[tid] = cont_b[tid];
    if (tid < AH) { biasA[tid] = attn_b1[tid]; w2a_s[tid] = attn_W2[tid]; }
    for (int i = tid; i < HID; i += 512) biasV[i] = val_b1[i];
    if (tid < ROWSF) {
        int gr = gr0 + tid;
        ridx[tid] = res_idx[gr];
        sidx[tid] = ss_idx[gr];
        float d = dist[gr];
        if (d != d) d = 0.0f;
        feat[tid * 6 + 0] = d * (1.0f / 15.0f);
        feat[tid * 6 + 1] = log1pf(fabsf((float)seq_sep[gr])) * 0.2f;
        float4 a = ((const float4*)angles)[gr];
        feat[tid * 6 + 2] = (a.x != a.x) ? 0.0f : a.x;
        feat[tid * 6 + 3] = (a.y != a.y) ? 0.0f : a.y;
        feat[tid * 6 + 4] = (a.z != a.z) ? 0.0f : a.z;
        feat[tid * 6 + 5] = (a.w != a.w) ? 0.0f : a.w;
    }
    __syncthreads();

    // ---------- phase 1: build comb with k-major row permutation rt=(j%5)*32+(j/5) ----------
    for (int i = tid; i < ROWSF * 64; i += 512) {
        int j = i >> 6, c = i & 63;
        int rt = (j % 5) * 32 + (j / 5);
        comb[rt * CLD + c] = __uint_as_float(f2tf(res_table[ridx[j] * 64 + c]));
    }
    for (int i = tid; i < ROWSF * 32; i += 512) {
        int j = i >> 5, c = i & 31;
        int rt = (j % 5) * 32 + (j / 5);
        comb[rt * CLD + 64 + c] = __uint_as_float(f2tf(ss_table[sidx[j] * 32 + c]));
    }
    for (int i = tid; i < ROWSF * 32; i += 512) {
        int j = i >> 5, c = i & 31;
        int rt = (j % 5) * 32 + (j / 5);
        float s = cbs[c];
        #pragma unroll
        for (int jj = 0; jj < 6; jj++) s += feat[j * 6 + jj] * cWs[jj * 32 + c];
        comb[rt * CLD + 96 + c] = __uint_as_float(f2tf(s));
    }
    for (int i = tid; i < AH * COMB; i += 512) {
        int k = i >> 7, n = i & 127;
        Ws[n * CLD + k] = __uint_as_float(f2tf(attn_W1[k * AH + n]));
    }
    __syncthreads();

    // ---------- phase 2: GEMM1 (attention scores), no atomics ----------
    {
        float acc[5][2][4];
        #pragma unroll
        for (int mi = 0; mi < 5; mi++)
            #pragma unroll
            for (int ni = 0; ni < 2; ni++)
                #pragma unroll
                for (int q = 0; q < 4; q++) acc[mi][ni][q] = 0.0f;

        #pragma unroll 2
        for (int ks = 0; ks < 16; ks++) {
            int kb = ks * 8;
            uint32 a[5][4];
            #pragma unroll
            for (int mi = 0; mi < 5; mi++) {
                const uint32* base = combu + (mrow0 + mi * 16) * CLD + kb + t;
                a[mi][0] = base[0];
                a[mi][1] = base[8 * CLD];
                a[mi][2] = base[4];
                a[mi][3] = base[8 * CLD + 4];
            }
            uint32 bb[2][2];
            #pragma unroll
            for (int ni = 0; ni < 2; ni++) {
                const uint32* bp = wsu + (nb + ni * 8 + g) * CLD + kb + t;
                bb[ni][0] = bp[0];
                bb[ni][1] = bp[4];
            }
            #pragma unroll
            for (int mi = 0; mi < 5; mi++)
                #pragma unroll
                for (int ni = 0; ni < 2; ni++)
                    mma_tf32(acc[mi][ni], a[mi], bb[ni]);
        }
        // per-thread partial over this warp's 4 cols, shfl-reduce over t-quad
        #pragma unroll
        for (int mi = 0; mi < 5; mi++) {
            #pragma unroll
            for (int rh = 0; rh < 2; rh++) {
                int row = mrow0 + mi * 16 + 8 * rh;   // tile row
                float p = 0.0f;
                #pragma unroll
                for (int ni = 0; ni < 2; ni++) {
                    #pragma unroll
                    for (int c = 0; c < 2; c++) {
                        int col = nb + ni * 8 + 2 * t + c;
                        p += gelu_exact(acc[mi][ni][rh * 2 + c] + biasA[col]) * w2a_s[col];
                    }
                }
                p += __shfl_xor_sync(0xFFFFFFFFu, p, 1);
                p += __shfl_xor_sync(0xFFFFFFFFu, p, 2);
                if (t == 0) P[row * 9 + wn] = p;     // part_s[160][9]
            }
        }
    }
    __syncthreads();
    if (tid < ROWSF) {
        float s = 0.0f;
        #pragma unroll
        for (int w = 0; w < 8; w++) s += P[tid * 9 + w];
        score_s[tid] = s;
    }
    __syncthreads();

    // ---------- phase 3: softmax (tid<32, row index = k*32+b) + stage val_W1 half0 ----------
    if (tid < TILE_B) {
        int gb = b0 + tid;
        float ab2 = attn_b2[0];
        int fu8 = g_flag_u8, ff32 = g_flag_f32;
        float s[KNB];
        int any = 0;
        #pragma unroll
        for (int k = 0; k < KNB; k++) {
            int idx = gb * KNB + k;
            int v;
            if (ff32)      v = (((const float*)validp)[idx] != 0.0f);
            else if (fu8)  v = (((const unsigned char*)validp)[idx] != 0);
            else           v = (((const int*)validp)[idx] != 0);
            any |= v;
            s[k] = v ? (score_s[k * 32 + tid] + ab2) : -10000.0f;
        }
        float m = s[0];
        #pragma unroll
        for (int k = 1; k < KNB; k++) m = fmaxf(m, s[k]);
        float e[KNB], sum = 0.0f;
        #pragma unroll
        for (int k = 0; k < KNB; k++) { e[k] = expf(s[k] - m); sum += e[k]; }
        float inv = 1.0f / sum;
        #pragma unroll
        for (int k = 0; k < KNB; k++) wgt_s[k * 32 + tid] = e[k] * inv;
        g_anyv[gb] = (unsigned char)any;
    }
    for (int i = tid; i < 128 * COMB; i += 512) {
        int k = i >> 7, n = i & 127;
        Ws[n * CLD + k] = __uint_as_float(f2tf(val_W1[k * HID + n]));
    }
    __syncthreads();

    // ---------- phases 4-5: GEMM2 halves, register-local weighted 5:1 reduce ----------
    #pragma unroll 1
    for (int half = 0; half < 2; half++) {
        if (half == 1) {
            for (int i = tid; i < 128 * COMB; i += 512) {
                int k = i >> 7, n = i & 127;
                Ws[n * CLD + k] = __uint_as_float(f2tf(val_W1[k * HID + 128 + n]));
            }
            __syncthreads();
        }
        float acc[5][2][4];
        #pragma unroll
        for (int mi = 0; mi < 5; mi++)
            #pragma unroll
            for (int ni = 0; ni < 2; ni++)
                #pragma unroll
                for (int q = 0; q < 4; q++) acc[mi][ni][q] = 0.0f;

        #pragma unroll 2
        for (int ks = 0; ks < 16; ks++) {
            int kb = ks * 8;
            uint32 a[5][4];
            #pragma unroll
            for (int mi = 0; mi < 5; mi++) {
                const uint32* base = combu + (mrow0 + mi * 16) * CLD + kb + t;
                a[mi][0] = base[0];
                a[mi][1] = base[8 * CLD];
                a[mi][2] = base[4];
                a[mi][3] = base[8 * CLD + 4];
            }
            uint32 bb[2][2];
            #pragma unroll
            for (int ni = 0; ni < 2; ni++) {
                const uint32* bp = wsu + (nb + ni * 8 + g) * CLD + kb + t;
                bb[ni][0] = bp[0];
                bb[ni][1] = bp[4];
            }
            #pragma unroll
            for (int mi = 0; mi < 5; mi++)
                #pragma unroll
                for (int ni = 0; ni < 2; ni++)
                    mma_tf32(acc[mi][ni], a[mi], bb[ni]);
        }
        // epilogue: rows = wm*80 + mi*16 + g + 8rh = k*32 + b ; accumulate per (b,col) in regs
        float hb[4][4];
        #pragma unroll
        for (int lb = 0; lb < 4; lb++)
            #pragma unroll
            for (int cc = 0; cc < 4; cc++) hb[lb][cc] = 0.0f;
        #pragma unroll
        for (int mi = 0; mi < 5; mi++) {
            #pragma unroll
            for (int rh = 0; rh < 2; rh++) {
                int row = mrow0 + mi * 16 + 8 * rh;
                float wk = wgt_s[row];
                int lb = (row & 31) >> 3;      // b = g + 8*lb
                #pragma unroll
                for (int ni = 0; ni < 2; ni++) {
                    #pragma unroll
                    for (int c = 0; c < 2; c++) {
                        int col = nb + ni * 8 + 2 * t + c;
                        hb[lb][ni * 2 + c] += wk * gelu_exact(acc[mi][ni][rh * 2 + c] + biasV[half * 128 + col]);
                    }
                }
            }
        }
        __syncthreads();   // protect P reuse (GEMM1 partials / previous half)
        #pragma unroll
        for (int lb = 0; lb < 4; lb++) {
            int b = g + 8 * lb;
            #pragma unroll
            for (int ni = 0; ni < 2; ni++)
                #pragma unroll
                for (int c = 0; c < 2; c++)
                    P[wm * 4160 + b * 130 + nb + ni * 8 + 2 * t + c] = hb[lb][ni * 2 + c];
        }
        __syncthreads();
        // combine wm halves -> hbar_s (each (b,col) exactly once)
        for (int i = tid; i < TILE_B * 128; i += 512) {
            int b = i >> 7, col = i & 127;
            hbar_s[b * 260 + half * 128 + col] = P[b * 130 + col] + P[4160 + b * 130 + col];
        }
    }
    __syncthreads();

    // ---------- phase 6: write hbar tile to gmem ----------
    for (int i = tid; i < TILE_B * HID / 4; i += 512) {
        int r = i >> 6, q = i & 63;
        float4 v = *(const float4*)&hbar_s[r * 260 + q * 4];
        *(float4*)&g_hbar[(size_t)(b0 + r) * HID + q * 4] = v;
    }
}

// ---------------- out kernel: out = hbar @ val_W2 + b2 (or fallback) ----------------
#define SMEM_O_FLOATS 51200
#define SMEM_O_BYTES (SMEM_O_FLOATS * 4)
#define TILE_M 128

__global__ void __launch_bounds__(512, 1) out_kernel(
    const float* __restrict__ val_W2,
    const float* __restrict__ val_b2,
    const float* __restrict__ fallback,
    float* __restrict__ out)
{
    extern __shared__ float sm[];
    float* As  = sm;            // A[r][k] tf32
    float* Ws  = sm + 16896;    // B[n][k] tf32
    float* b2s = sm + 50688;
    float* fbs = sm + 50944;

    const int tid  = threadIdx.x;
    const int lane = tid & 31;
    const int warp = tid >> 5;
    const int g    = lane >> 2;
    const int t    = lane & 3;
    const int wm   = warp >> 2;   // 0..3 (32 rows each)
    const int wn   = warp & 3;    // 0..3 (64 cols each)
    const int m0   = blockIdx.x * TILE_M;

    const uint32* au = (const uint32*)As;
    const uint32* wu = (const uint32*)Ws;

    for (int i = tid; i < HID; i += 512) { b2s[i] = val_b2[i]; fbs[i] = fallback[i]; }

    float acc[2][8][4];
    #pragma unroll
    for (int mi = 0; mi < 2; mi++)
        #pragma unroll
        for (int ni = 0; ni < 8; ni++)
            #pragma unroll
            for (int q = 0; q < 4; q++) acc[mi][ni][q] = 0.0f;

    #pragma unroll 1
    for (int kc = 0; kc < HID; kc += 128) {
        __syncthreads();
        for (int i = tid; i < TILE_M * 128; i += 512) {
            int r = i >> 7, kk = i & 127;
            As[r * CLD + kk] = __uint_as_float(f2tf(g_hbar[(size_t)(m0 + r) * HID + kc + kk]));
        }
        for (int i = tid; i < HID * 128; i += 512) {
            int kk = i >> 8, n = i & 255;
            Ws[n * CLD + kk] = __uint_as_float(f2tf(val_W2[(size_t)(kc + kk) * HID + n]));
        }
        __syncthreads();
        #pragma unroll 2
        for (int ks = 0; ks < 16; ks++) {
            int kb = ks * 8;
            uint32 a[2][4];
            #pragma unroll
            for (int mi = 0; mi < 2; mi++) {
                const uint32* base = au + (wm * 32 + mi * 16 + g) * CLD + kb + t;
                a[mi][0] = base[0];
                a[mi][1] = base[8 * CLD];
                a[mi][2] = base[4];
                a[mi][3] = base[8 * CLD + 4];
            }
            uint32 bb[8][2];
            #pragma unroll
            for (int ni = 0; ni < 8; ni++) {
                const uint32* bp = wu + (wn * 64 + ni * 8 + g) * CLD + kb + t;
                bb[ni][0] = bp[0];
                bb[ni][1] = bp[4];
            }
            #pragma unroll
            for (int mi = 0; mi < 2; mi++)
                #pragma unroll
                for (int ni = 0; ni < 8; ni++)
                    mma_tf32(acc[mi][ni], a[mi], bb[ni]);
        }
    }

    #pragma unroll
    for (int mi = 0; mi < 2; mi++) {
        #pragma unroll
        for (int rh = 0; rh < 2; rh++) {
            int row = m0 + wm * 32 + mi * 16 + g + 8 * rh;
            int av = g_anyv[row];
            #pragma unroll
            for (int ni = 0; ni < 8; ni++) {
                int colb = wn * 64 + ni * 8 + 2 * t;
                float x0 = acc[mi][ni][rh * 2 + 0];
                float x1 = acc[mi][ni][rh * 2 + 1];
                float2 o;
                if (av) { o.x = x0 + b2s[colb]; o.y = x1 + b2s[colb + 1]; }
                else    { o.x = fbs[colb];      o.y = fbs[colb + 1]; }
                *(float2*)(out + (size_t)row * HID + colb) = o;
            }
        }
    }
}

// ---------------- launch ----------------
extern "C" void kernel_launch(void* const* d_in, const int* in_sizes, int n_in,
                              void* d_out, int out_size)
{
    const int*   res_idx   = (const int*)d_in[0];
    const int*   ss_idx    = (const int*)d_in[1];
    const float* dist      = (const float*)d_in[2];
    const int*   seq_sep   = (const int*)d_in[3];
    const float* angles    = (const float*)d_in[4];
    const void*  validp    = d_in[5];
    const float* res_table = (const float*)d_in[6];
    const float* ss_table  = (const float*)d_in[7];
    const float* cont_W    = (const float*)d_in[8];
    const float* cont_b    = (const float*)d_in[9];
    const float* attn_W1   = (const float*)d_in[10];
    const float* attn_b1   = (const float*)d_in[11];
    const float* attn_W2   = (const float*)d_in[12];
    const float* attn_b2   = (const float*)d_in[13];
    const float* val_W1    = (const float*)d_in[14];
    const float* val_b1    = (const float*)d_in[15];
    const float* val_W2    = (const float*)d_in[16];
    const float* val_b2    = (const float*)d_in[17];
    const float* fallback  = (const float*)d_in[18];
    float* out = (float*)d_out;

    cudaFuncSetAttribute(fused_kernel, cudaFuncAttributeMaxDynamicSharedMemorySize, SMEM_F_BYTES);
    cudaFuncSetAttribute(out_kernel,   cudaFuncAttributeMaxDynamicSharedMemorySize, SMEM_O_BYTES);

    reset_flags<<<1, 1>>>();
    detect_valid<<<148, 1024>>>((const unsigned int*)validp, (B_TOTAL * KNB) / 4);

    fused_kernel<<<B_TOTAL / TILE_B, 512, SMEM_F_BYTES>>>(
        res_idx, ss_idx, dist, seq_sep, angles, validp,
        res_table, ss_table, cont_W, cont_b,
        attn_W1, attn_b1, attn_W2, attn_b2, val_W1, val_b1);

    out_kernel<<<B_TOTAL / TILE_M, 512, SMEM_O_BYTES>>>(val_W2, val_b2, fallback, out);
}